// round 8
// baseline (speedup 1.0000x reference)
#include <cuda_runtime.h>
#include <cuda_bf16.h>
#include <math.h>
#include <stdint.h>

// Problem shapes (fixed)
#define BDIM 32
#define SDIM 2048
#define HDIM 512
#define EDIM 512
#define ROWS (BDIM * SDIM)   // 65536
#define MTILES (ROWS / 128)  // 512 m-tiles; 16 per batch

// Scratch (device globals: allocation-free rule)
__device__ float g_w[ROWS];
__device__ float g_denInv[ROWS];
__device__ float g_tsum[(size_t)MTILES * EDIM];  // per (m-tile, col) 128-row sums
__device__ unsigned g_flag[MTILES * 2];          // publish flags per (m-tile, n-block)

// ======================= helpers =======================
__device__ __forceinline__ uint32_t smem_u32(const void* p) {
    uint32_t a;
    asm("{ .reg .u64 t; cvta.to.shared.u64 t, %1; cvt.u32.u64 %0, t; }" : "=r"(a) : "l"(p));
    return a;
}
__device__ __forceinline__ void cp16(void* sdst, const void* gsrc) {
    uint32_t d = smem_u32(sdst);
    asm volatile("cp.async.cg.shared.global [%0], [%1], 16;" :: "r"(d), "l"(gsrc) : "memory");
}
#define CP_COMMIT() asm volatile("cp.async.commit_group;" ::: "memory")
#define CP_WAIT(n)  asm volatile("cp.async.wait_group %0;" :: "n"(n) : "memory")

__device__ __forceinline__ uint32_t f2tf32(float f) {
    uint32_t o;
    asm("cvt.rna.tf32.f32 %0, %1;" : "=r"(o) : "f"(f));
    return o;
}
__device__ __forceinline__ void mma_tf32(float* c, const uint32_t* a, const uint32_t* b) {
    asm volatile(
        "mma.sync.aligned.m16n8k8.row.col.f32.tf32.tf32.f32 "
        "{%0,%1,%2,%3}, {%4,%5,%6,%7}, {%8,%9}, {%0,%1,%2,%3};"
        : "+f"(c[0]), "+f"(c[1]), "+f"(c[2]), "+f"(c[3])
        : "r"(a[0]), "r"(a[1]), "r"(a[2]), "r"(a[3]), "r"(b[0]), "r"(b[1]));
}

// ======================= Kernel 0: reset look-back flags =======================
__global__ void RA_reset_kernel() {
    g_flag[threadIdx.x] = 0u;
}

// ======================= Kernel 1: w = exp(alpha . Wa + ba) =======================
__global__ void RA_w_kernel(const float* __restrict__ alpha, const float* __restrict__ Wa,
                            const float* __restrict__ ba) {
    __shared__ __align__(16) float sWa[HDIM];
    int tid = threadIdx.x;
    for (int i = tid; i < HDIM; i += blockDim.x) sWa[i] = Wa[i];
    __syncthreads();
    int wid = tid >> 5, lane = tid & 31;
    int row = blockIdx.x * 8 + wid;
    const float4* a4 = (const float4*)(alpha + (size_t)row * HDIM);
    const float4* w4 = (const float4*)sWa;
    float sum = 0.f;
#pragma unroll
    for (int i = 0; i < 4; i++) {
        float4 a = a4[lane + i * 32];
        float4 w = w4[lane + i * 32];
        sum += a.x * w.x + a.y * w.y + a.z * w.z + a.w * w.w;
    }
#pragma unroll
    for (int o = 16; o > 0; o >>= 1) sum += __shfl_xor_sync(0xffffffffu, sum, o);
    if (lane == 0) g_w[row] = expf(sum + ba[0]);
}

// ======================= Kernel 2: denInv = 1/(cumsum(w)+1e-10), per b =======================
__global__ void RA_den_kernel() {
    __shared__ float sw[SDIM];
    __shared__ float sx[32];
    int b = blockIdx.x, tid = threadIdx.x;
    for (int i = tid; i < SDIM; i += 256) sw[i] = g_w[b * SDIM + i];
    __syncthreads();
    if (tid < 32) {
        int lane = tid;
        int base = lane * 64;
        float s = 0.f;
        for (int i = 0; i < 64; i++) { s += sw[base + i]; sw[base + i] = s; }
        float tot = s;
#pragma unroll
        for (int o = 1; o < 32; o <<= 1) {
            float t = __shfl_up_sync(0xffffffffu, tot, o);
            if (lane >= o) tot += t;
        }
        sx[lane] = tot - s;
    }
    __syncthreads();
    float* di = g_denInv + b * SDIM;
    for (int i = tid; i < SDIM; i += 256)
        di[i] = 1.0f / (sw[i] + sx[i >> 6] + 1e-10f);
}

// ======================= Kernel 3: fully fused GEMM + epilogue + single-pass scan =======================
// out[row, e] = (sum_{r<=row, same batch} w[r]*tanh(X[r]Wb[e]+bb[e])*embed[r,e]) * denInv[row]
#define MT 128
#define NT 256
#define KB 32
#define KT (HDIM / KB)   // 16 k-tiles
#define NSTAGE 3
#define LDA 36           // KB + 4 pad floats; conflict-free frags
#define A_ST_FL (MT * LDA)
#define B_ST_FL (NT * LDA)
#define ST_FL (A_ST_FL + B_ST_FL)
#define GEMM_SMEM_FL (NSTAGE * ST_FL + NT + 3 * NT)   // + bb + sCh0/sCh1/sPre
#define GEMM_SMEM (GEMM_SMEM_FL * 4)

__device__ __forceinline__ void gemm_load_stage(float* smem, int s, int kt,
                                                const float* __restrict__ A,
                                                const float* __restrict__ B,
                                                int m0, int n0, int tid) {
    float* sA = smem + s * ST_FL;
    float* sB = sA + A_ST_FL;
#pragma unroll
    for (int i = 0; i < 4; i++) {
        int id = tid + i * 256;
        int r = id >> 3, c4 = id & 7;
        cp16(sA + r * LDA + c4 * 4, A + (size_t)(m0 + r) * HDIM + kt * KB + c4 * 4);
    }
#pragma unroll
    for (int i = 0; i < 8; i++) {
        int id = tid + i * 256;
        int r = id >> 3, c4 = id & 7;
        cp16(sB + r * LDA + c4 * 4, B + (size_t)(n0 + r) * HDIM + kt * KB + c4 * 4);
    }
}

__global__ void __launch_bounds__(256, 1) RA_gemm_kernel(
    const float* __restrict__ Abeta,   // [ROWS, HDIM]
    const float* __restrict__ Wb,      // [EDIM, HDIM]
    const float* __restrict__ bb,      // [EDIM]
    const float* __restrict__ embed,   // [ROWS, EDIM]
    float* __restrict__ out)           // [ROWS, EDIM]
{
    extern __shared__ float smem[];
    int tid = threadIdx.x, wid = tid >> 5, lane = tid & 31;
    int g = lane >> 2, tg = lane & 3;
    int bx = blockIdx.x, by = blockIdx.y;
    int n0 = bx * NT, m0 = by * MT;
    int wm = wid & 1, wn = wid >> 1;   // 2 x 4 warp grid; warp tile 64x64
    int t_local = by & 15;             // m-tile index within its batch
    int mtile_base = by - t_local;

    float* sBB  = smem + NSTAGE * ST_FL;
    float* sCh0 = sBB + NT;
    float* sCh1 = sCh0 + NT;
    float* sPre = sCh1 + NT;
    if (tid < NT) sBB[tid] = bb[n0 + tid];

#pragma unroll
    for (int s = 0; s < NSTAGE - 1; s++) {
        gemm_load_stage(smem, s, s, Abeta, Wb, m0, n0, tid);
        CP_COMMIT();
    }

    float acc[4][8][4];
#pragma unroll
    for (int i = 0; i < 4; i++)
#pragma unroll
        for (int j = 0; j < 8; j++)
#pragma unroll
            for (int q = 0; q < 4; q++) acc[i][j][q] = 0.f;

    for (int kt = 0; kt < KT; kt++) {
        CP_WAIT(NSTAGE - 2);
        __syncthreads();
        if (kt + NSTAGE - 1 < KT)
            gemm_load_stage(smem, (kt + NSTAGE - 1) % NSTAGE, kt + NSTAGE - 1,
                            Abeta, Wb, m0, n0, tid);
        CP_COMMIT();

        int buf = kt % NSTAGE;
        const float* sA = smem + buf * ST_FL + (wm * 64 + g) * LDA + tg;
        const float* sB = smem + buf * ST_FL + A_ST_FL + (wn * 64 + g) * LDA + tg;
#pragma unroll
        for (int k8 = 0; k8 < KB / 8; k8++) {
            const float* pA = sA + k8 * 8;
            const float* pB = sB + k8 * 8;
            uint32_t a[4][4];
#pragma unroll
            for (int i = 0; i < 4; i++) {
                a[i][0] = f2tf32(pA[(i * 16 + 0) * LDA + 0]);
                a[i][1] = f2tf32(pA[(i * 16 + 8) * LDA + 0]);
                a[i][2] = f2tf32(pA[(i * 16 + 0) * LDA + 4]);
                a[i][3] = f2tf32(pA[(i * 16 + 8) * LDA + 4]);
            }
#pragma unroll
            for (int j = 0; j < 8; j++) {
                uint32_t b[2];
                b[0] = f2tf32(pB[j * 8 * LDA + 0]);
                b[1] = f2tf32(pB[j * 8 * LDA + 4]);
#pragma unroll
                for (int i = 0; i < 4; i++) mma_tf32(acc[i][j], a[i], b);
            }
        }
    }

    // ---- step 1: transform acc -> g values; accumulate per-column partial sums ----
    int m_base = m0 + wm * 64, n_base = n0 + wn * 64;
    float cs[8][2];
#pragma unroll
    for (int j = 0; j < 8; j++) { cs[j][0] = 0.f; cs[j][1] = 0.f; }

#pragma unroll
    for (int i = 0; i < 4; i++) {
#pragma unroll
        for (int r2 = 0; r2 < 2; r2++) {
            int row = m_base + i * 16 + r2 * 8 + g;
            float wr = g_w[row];
            const float* erow = embed + (size_t)row * EDIM;
#pragma unroll
            for (int j = 0; j < 8; j++) {
                int nc = n_base + j * 8 + tg * 2;
                float2 ee = *(const float2*)(erow + nc);
                float b0 = sBB[nc - n0], b1 = sBB[nc - n0 + 1];
                float vx = wr * tanhf(acc[i][j][r2 * 2 + 0] + b0) * ee.x;
                float vy = wr * tanhf(acc[i][j][r2 * 2 + 1] + b1) * ee.y;
                acc[i][j][r2 * 2 + 0] = vx;
                acc[i][j][r2 * 2 + 1] = vy;
                cs[j][0] += vx;
                cs[j][1] += vy;
            }
        }
    }
    // reduce over the 8 g-lanes -> 64-row chunk column sums (all lanes get it)
#pragma unroll
    for (int j = 0; j < 8; j++) {
#pragma unroll
        for (int q = 0; q < 2; q++) {
            float v = cs[j][q];
            v += __shfl_xor_sync(0xffffffffu, v, 4);
            v += __shfl_xor_sync(0xffffffffu, v, 8);
            v += __shfl_xor_sync(0xffffffffu, v, 16);
            cs[j][q] = v;
        }
    }
    // ---- step 2: stash chunk sums in smem (per wm half) ----
    if (g == 0) {
        float* dst = (wm == 0) ? sCh0 : sCh1;
#pragma unroll
        for (int j = 0; j < 8; j++) {
            int c = wn * 64 + j * 8 + tg * 2;
            dst[c] = cs[j][0];
            dst[c + 1] = cs[j][1];
        }
    }
    __syncthreads();

    // ---- step 3: publish 128-row tile sum + release flag ----
    {
        float ts = sCh0[tid] + sCh1[tid];
        g_tsum[(size_t)by * EDIM + n0 + tid] = ts;
    }
    __threadfence();
    __syncthreads();
    if (tid == 0)
        asm volatile("st.release.gpu.b32 [%0], %1;"
                     :: "l"(&g_flag[by * 2 + bx]), "r"(1u) : "memory");

    // ---- step 4: look-back (spin on predecessors, then accumulate) ----
    if (tid < t_local) {
        const unsigned* f = &g_flag[(mtile_base + tid) * 2 + bx];
        unsigned v;
        unsigned ns = 64;
        for (;;) {
            asm volatile("ld.acquire.gpu.b32 %0, [%1];" : "=r"(v) : "l"(f) : "memory");
            if (v) break;
            __nanosleep(ns);
            if (ns < 1024) ns <<= 1;
        }
    }
    __syncthreads();
    {
        float p = 0.f;
        for (int q = 0; q < t_local; q++)
            p += g_tsum[(size_t)(mtile_base + q) * EDIM + n0 + tid];
        sPre[tid] = p;
    }
    __syncthreads();

    // ---- step 5: interleaved in-warp prefix + divide + store ----
    // Chunk row = q*8 + g  (g = fast index!).  For each q in order:
    //   inclusive cross-g scan of this q's values, add carry, emit; carry += q total.
    float dinv[8];
#pragma unroll
    for (int q = 0; q < 8; q++) dinv[q] = g_denInv[m_base + q * 8 + g];

#pragma unroll
    for (int j = 0; j < 8; j++) {
        int c = wn * 64 + j * 8 + tg * 2;   // col - n0
        float carryx = sPre[c]     + (wm ? sCh0[c]     : 0.f);
        float carryy = sPre[c + 1] + (wm ? sCh0[c + 1] : 0.f);
#pragma unroll
        for (int q = 0; q < 8; q++) {
            int i = q >> 1, r2 = q & 1;
            float sxv = acc[i][j][r2 * 2 + 0];
            float syv = acc[i][j][r2 * 2 + 1];
#pragma unroll
            for (int o = 4; o <= 16; o <<= 1) {
                float ux = __shfl_up_sync(0xffffffffu, sxv, o);
                float uy = __shfl_up_sync(0xffffffffu, syv, o);
                if (lane >= o) { sxv += ux; syv += uy; }
            }
            float totx = __shfl_sync(0xffffffffu, sxv, 28 + tg);  // g=7 lane, same tg
            float toty = __shfl_sync(0xffffffffu, syv, 28 + tg);
            int row = m_base + q * 8 + g;
            float d = dinv[q];
            float2 r;
            r.x = (carryx + sxv) * d;
            r.y = (carryy + syv) * d;
            *(float2*)(out + (size_t)row * EDIM + n_base + j * 8 + tg * 2) = r;
            carryx += totx;
            carryy += toty;
        }
    }
}

// ======================= Host launch =======================
extern "C" void kernel_launch(void* const* d_in, const int* in_sizes, int n_in,
                              void* d_out, int out_size) {
    const float* alpha   = (const float*)d_in[0];
    const float* beta_in = (const float*)d_in[1];
    const float* embed   = (const float*)d_in[2];
    const float* Wb      = (const float*)d_in[3];
    const float* bb      = (const float*)d_in[4];
    const float* Wa      = (const float*)d_in[5];
    const float* ba      = (const float*)d_in[6];
    float* out = (float*)d_out;

    RA_reset_kernel<<<1, MTILES * 2>>>();
    RA_w_kernel<<<ROWS / 8, 256>>>(alpha, Wa, ba);
    RA_den_kernel<<<BDIM, 256>>>();
    cudaFuncSetAttribute(RA_gemm_kernel, cudaFuncAttributeMaxDynamicSharedMemorySize, GEMM_SMEM);
    RA_gemm_kernel<<<dim3(EDIM / NT, ROWS / MT), 256, GEMM_SMEM>>>(beta_in, Wb, bb, embed, out);
    (void)in_sizes; (void)n_in; (void)out_size;
}